// round 2
// baseline (speedup 1.0000x reference)
#include <cuda_runtime.h>

#define THREADS 128
#define RPT 8           // rows per thread; THREADS*RPT == 1024 == S
#define TC 128          // columns per shared tile
#define SD 1024

// scratch (no allocations allowed): rowmin bits + accumulators
__device__ int   g_rowmin[24576];   // 8*1024 (chamfer1) + 16*1024 (chamfer2)
__device__ float g_acc[4];          // [0]=colsum1, [1]=colsum2, [2]=mse_sum

__global__ void k_init() {
    int i = blockIdx.x * blockDim.x + threadIdx.x;
    if (i < 24576) g_rowmin[i] = 0x7f800000;   // +inf
    if (i < 4) g_acc[i] = 0.0f;
}

__global__ __launch_bounds__(THREADS)
void k_chamfer(const float* __restrict__ pa,   // [BB, 1024, 3]  (rows: "structure")
               const float* __restrict__ pb,   // [BB, N, 3]     (cols: "gt")
               int N, int rowmin_off, int acc_idx, int cchunk)
{
    __shared__ float4 tile[TC];
    __shared__ float  wmin[4][TC];
    __shared__ float  wsum[4];

    const int b    = blockIdx.y;
    const int col0 = blockIdx.x * cchunk;
    const int tid  = threadIdx.x;
    const int lane = tid & 31;
    const int warp = tid >> 5;
    const float INF = __int_as_float(0x7f800000);

    // per-thread rows: negated coords + half squared norm
    float nax[RPT], nay[RPT], naz[RPT], ha[RPT], rmin[RPT];
    const float* pab = pa + (size_t)b * SD * 3;
#pragma unroll
    for (int i = 0; i < RPT; i++) {
        int r = tid * RPT + i;
        float x = pab[r*3+0], y = pab[r*3+1], z = pab[r*3+2];
        nax[i] = -x; nay[i] = -y; naz[i] = -z;
        ha[i]  = 0.5f * (x*x + y*y + z*z);
        rmin[i] = INF;
    }

    float csum = 0.0f;
    const float* pbb = pb + (size_t)b * (size_t)N * 3;

    for (int t0 = 0; t0 < cchunk; t0 += TC) {
        __syncthreads();   // previous tile + wmin fully consumed
        {
            int c = col0 + t0 + tid;     // TC == THREADS
            float x = pbb[c*3+0], y = pbb[c*3+1], z = pbb[c*3+2];
            tile[tid] = make_float4(x, y, z, 0.5f*(x*x + y*y + z*z));
        }
        __syncthreads();

#pragma unroll 4
        for (int j = 0; j < TC; j++) {
            float4 p = tile[j];          // broadcast LDS.128
            float cmin = INF;
#pragma unroll
            for (int i = 0; i < RPT; i++) {
                // t = ha + hb - dot(a,b);  dist = 2t  (min-preserving scale)
                float t = fmaf(nax[i], p.x,
                          fmaf(nay[i], p.y,
                          fmaf(naz[i], p.z, ha[i] + p.w)));
                rmin[i] = fminf(rmin[i], t);
                cmin    = fminf(cmin, t);
            }
#pragma unroll
            for (int o = 16; o > 0; o >>= 1)
                cmin = fminf(cmin, __shfl_xor_sync(0xffffffffu, cmin, o));
            if (lane == 0) wmin[warp][j] = cmin;
        }
        __syncthreads();
        // column tid of this tile: combine the 4 warp partial mins (exact over S)
        csum += fminf(fminf(wmin[0][tid], wmin[1][tid]),
                      fminf(wmin[2][tid], wmin[3][tid]));
    }

    // partial row mins -> global (positive floats: int compare is order-preserving)
#pragma unroll
    for (int i = 0; i < RPT; i++) {
        int r = tid * RPT + i;
        atomicMin(&g_rowmin[rowmin_off + b * SD + r], __float_as_int(rmin[i]));
    }

    // block-reduce the column-min sum, one atomicAdd per block
#pragma unroll
    for (int o = 16; o > 0; o >>= 1)
        csum += __shfl_xor_sync(0xffffffffu, csum, o);
    if (lane == 0) wsum[warp] = csum;
    __syncthreads();
    if (tid == 0)
        atomicAdd(&g_acc[acc_idx], wsum[0] + wsum[1] + wsum[2] + wsum[3]);
}

// consistency: tmp[t,b,s,e] = sum_d sp[b,s,d]*M[t,d,e];  MSE vs tsp, *1000
__global__ void k_consist(const float* __restrict__ sp,
                          const float* __restrict__ tsp,
                          const float* __restrict__ M)
{
    int idx = blockIdx.x * blockDim.x + threadIdx.x;   // 0 .. 16383 = T*B*S
    int t  = idx >> 13;           // / 8192
    int bs = idx & 8191;
    const float* p = sp + (size_t)bs * 3;
    float x = p[0], y = p[1], z = p[2];
    const float* m = M + t * 9;
    const float* q = tsp + (size_t)idx * 3;
    float e = 0.0f;
#pragma unroll
    for (int c = 0; c < 3; c++) {
        float v = fmaf(x, m[c], fmaf(y, m[3 + c], z * m[6 + c]));
        float d = v - q[c];
        e = fmaf(d, d, e);
    }
#pragma unroll
    for (int o = 16; o > 0; o >>= 1)
        e += __shfl_xor_sync(0xffffffffu, e, o);
    __shared__ float ws[8];
    int lane = threadIdx.x & 31, warp = threadIdx.x >> 5;
    if (lane == 0) ws[warp] = e;
    __syncthreads();
    if (threadIdx.x == 0) {
        float s = 0.0f;
        for (int w = 0; w < (int)(blockDim.x >> 5); w++) s += ws[w];
        atomicAdd(&g_acc[2], s);
    }
}

__global__ void k_final(float* __restrict__ out) {
    __shared__ float sh[256];
    int tid = threadIdx.x;
    float a1 = 0.0f, a2 = 0.0f;
    for (int i = tid; i < 8192;  i += 256) a1 += __int_as_float(g_rowmin[i]);
    for (int i = tid; i < 16384; i += 256) a2 += __int_as_float(g_rowmin[8192 + i]);

    sh[tid] = a1; __syncthreads();
    for (int s = 128; s > 0; s >>= 1) { if (tid < s) sh[tid] += sh[tid + s]; __syncthreads(); }
    float rs1 = sh[0];
    __syncthreads();
    sh[tid] = a2; __syncthreads();
    for (int s = 128; s > 0; s >>= 1) { if (tid < s) sh[tid] += sh[tid + s]; __syncthreads(); }
    float rs2 = sh[0];

    if (tid == 0) {
        // dist = 2*t; cd = (mean_rowmin + mean_colmin)/2 = rs/cnt_r + cs/cnt_c (t-units)
        float cd1 = rs1 / 8192.0f  + g_acc[0] / 131072.0f;   // 8*1024, 8*16384
        float cd2 = rs2 / 16384.0f + g_acc[1] / 262144.0f;   // 16*1024, 16*16384
        float consist = g_acc[2] * (1000.0f / 49152.0f);     // mean over T*B*S*D
        out[0] = (cd1 + cd2) / 3.0f + consist;               // /(T+1)
    }
}

extern "C" void kernel_launch(void* const* d_in, const int* in_sizes, int n_in,
                              void* d_out, int out_size) {
    const float* gt  = (const float*)d_in[0];   // [8,16384,3]
    const float* sp  = (const float*)d_in[1];   // [8,1024,3]
    const float* tgt = (const float*)d_in[2];   // [2,8,16384,3] -> [16,16384,3]
    const float* tsp = (const float*)d_in[3];   // [2,8,1024,3]  -> [16,1024,3]
    const float* M   = (const float*)d_in[4];   // [2,3,3]

    (void)in_sizes; (void)n_in; (void)out_size;

    k_init<<<96, 256>>>();
    const int CCHUNK = 512;
    k_chamfer<<<dim3(16384 / CCHUNK, 8),  THREADS>>>(sp,  gt,  16384, 0,    0, CCHUNK);
    k_chamfer<<<dim3(16384 / CCHUNK, 16), THREADS>>>(tsp, tgt, 16384, 8192, 1, CCHUNK);
    k_consist<<<64, 256>>>(sp, tsp, M);
    k_final<<<1, 256>>>((float*)d_out);
}

// round 3
// speedup vs baseline: 1.8686x; 1.8686x over previous
#include <cuda_runtime.h>

#define SD 1024          // structure points per batch (rows)
#define NP 16384         // gt points per batch (cols)
#define WC 64            // columns per warp
#define TILE 32          // columns per staged tile (== warp size)
#define WARPS 4          // warps per block
#define COLS_PER_BLOCK (WARPS * WC)   // 256

// scratch (no allocations allowed)
__device__ int   g_rowmin[24576];   // 8*1024 (chamfer1) + 16*1024 (chamfer2), float bits
__device__ float g_acc[4];          // [0]=colsum1, [1]=colsum2, [2]=mse_sum

__device__ __forceinline__ unsigned long long pack2(float lo, float hi) {
    unsigned long long r;
    asm("mov.b64 %0, {%1, %2};" : "=l"(r) : "f"(lo), "f"(hi));
    return r;
}

// two pairs: q = (nax,nay,naz).(px,py,pz) + ha + hb  (all packed f32x2),
// update row-mins (lo/hi) and running column-min.
__device__ __forceinline__ void pair_step(
    unsigned long long nax2, unsigned long long nay2, unsigned long long naz2,
    unsigned long long ha2,
    unsigned long long px2, unsigned long long py2, unsigned long long pz2,
    unsigned long long hb2,
    float& rlo, float& rhi, float& cm)
{
    asm("{\n\t"
        ".reg .b64 q;\n\t"
        ".reg .f32 lo, hi;\n\t"
        "fma.rn.f32x2 q, %5, %9, %6;\n\t"   // naz2*pz2 + ha2
        "fma.rn.f32x2 q, %4, %8, q;\n\t"    // + nay2*py2
        "fma.rn.f32x2 q, %3, %7, q;\n\t"    // + nax2*px2
        "add.rn.f32x2 q, q, %10;\n\t"       // + hb2
        "mov.b64 {lo, hi}, q;\n\t"
        "min.f32 %0, %0, lo;\n\t"
        "min.f32 %1, %1, hi;\n\t"
        "min.f32 %2, %2, lo;\n\t"
        "min.f32 %2, %2, hi;\n\t"
        "}"
        : "+f"(rlo), "+f"(rhi), "+f"(cm)
        : "l"(nax2), "l"(nay2), "l"(naz2), "l"(ha2),
          "l"(px2), "l"(py2), "l"(pz2), "l"(hb2));
}

// k_pre: single block. Inits g_rowmin/g_acc AND computes the consistency MSE sum.
__global__ __launch_bounds__(1024)
void k_pre(const float* __restrict__ sp,
           const float* __restrict__ tsp,
           const float* __restrict__ M)
{
    int tid = threadIdx.x;
    for (int i = tid; i < 24576; i += 1024) g_rowmin[i] = 0x7f800000;
    if (tid < 2) g_acc[tid] = 0.0f;

    // consistency: 16384 items, 16 per thread
    float e = 0.0f;
#pragma unroll
    for (int k = 0; k < 16; k++) {
        int idx = tid + k * 1024;          // [0, 16384)
        int t  = idx >> 13;
        int bs = idx & 8191;
        const float* p = sp + (size_t)bs * 3;
        float x = p[0], y = p[1], z = p[2];
        const float* m = M + t * 9;
        const float* q = tsp + (size_t)idx * 3;
#pragma unroll
        for (int c = 0; c < 3; c++) {
            float v = fmaf(x, m[c], fmaf(y, m[3 + c], z * m[6 + c]));
            float d = v - q[c];
            e = fmaf(d, d, e);
        }
    }
    __shared__ float sh[1024];
    sh[tid] = e; __syncthreads();
    for (int s = 512; s > 0; s >>= 1) {
        if (tid < s) sh[tid] += sh[tid + s];
        __syncthreads();
    }
    if (tid == 0) g_acc[2] = sh[0];
}

__global__ __launch_bounds__(WARPS * 32)
void k_chamfer(const float* __restrict__ pa,   // [BB, 1024, 3] rows
               const float* __restrict__ pb,   // [BB, 16384, 3] cols
               int rowmin_off, int acc_idx)
{
    __shared__ float4 tile[WARPS][TILE];

    const int b    = blockIdx.y;
    const int tid  = threadIdx.x;
    const int lane = tid & 31;
    const int warp = tid >> 5;
    const float INF = __int_as_float(0x7f800000);

    // ---- load ALL 1024 rows of this batch into this warp's registers ----
    // lane l holds rows { i*32 + l : i in [0,32) }, packed in pairs (2i, 2i+1).
    unsigned long long nax2[16], nay2[16], naz2[16], ha2[16];
    float rl[16], rh[16];
    const float* pab = pa + (size_t)b * SD * 3;
#pragma unroll
    for (int i = 0; i < 16; i++) {
        int r0 = (2 * i) * 32 + lane;
        int r1 = r0 + 32;
        float x0 = pab[r0*3+0], y0 = pab[r0*3+1], z0 = pab[r0*3+2];
        float x1 = pab[r1*3+0], y1 = pab[r1*3+1], z1 = pab[r1*3+2];
        nax2[i] = pack2(-x0, -x1);
        nay2[i] = pack2(-y0, -y1);
        naz2[i] = pack2(-z0, -z1);
        ha2[i]  = pack2(0.5f * (x0*x0 + y0*y0 + z0*z0),
                        0.5f * (x1*x1 + y1*y1 + z1*z1));
        rl[i] = INF; rh[i] = INF;
    }

    const float* pbb = pb + (size_t)b * NP * 3;
    const int cbase = blockIdx.x * COLS_PER_BLOCK + warp * WC;

    // prefetch first tile's column into regs
    int c = cbase + lane;
    float cx = pbb[c*3+0], cy = pbb[c*3+1], cz = pbb[c*3+2];

    float csum = 0.0f;

#pragma unroll
    for (int t = 0; t < WC / TILE; t++) {
        tile[warp][lane] = make_float4(cx, cy, cz,
                                       0.5f * (cx*cx + cy*cy + cz*cz));
        __syncwarp();
        if (t + 1 < WC / TILE) {           // prefetch next tile
            int cn = cbase + (t + 1) * TILE + lane;
            cx = pbb[cn*3+0]; cy = pbb[cn*3+1]; cz = pbb[cn*3+2];
        }

#pragma unroll 2
        for (int j = 0; j < TILE; j++) {
            float4 p = tile[warp][j];          // broadcast LDS.128
            unsigned long long px2 = pack2(p.x, p.x);
            unsigned long long py2 = pack2(p.y, p.y);
            unsigned long long pz2 = pack2(p.z, p.z);
            unsigned long long hb2 = pack2(p.w, p.w);
            float cm = INF;
#pragma unroll
            for (int i = 0; i < 16; i++)
                pair_step(nax2[i], nay2[i], naz2[i], ha2[i],
                          px2, py2, pz2, hb2, rl[i], rh[i], cm);
            // warp covers the full 1024 rows -> this reduce completes the col-min
#pragma unroll
            for (int o = 16; o > 0; o >>= 1)
                cm = fminf(cm, __shfl_xor_sync(0xffffffffu, cm, o));
            if (lane == 0) csum += cm;
        }
        __syncwarp();
    }

    if (lane == 0) atomicAdd(&g_acc[acc_idx], csum);

    // partial row-mins -> global (positive floats: int compare order-preserving)
    int* rm = g_rowmin + rowmin_off + b * SD;
#pragma unroll
    for (int i = 0; i < 16; i++) {
        int r0 = (2 * i) * 32 + lane;
        atomicMin(&rm[r0],      __float_as_int(rl[i]));
        atomicMin(&rm[r0 + 32], __float_as_int(rh[i]));
    }
}

__global__ __launch_bounds__(256)
void k_final(float* __restrict__ out) {
    __shared__ float sh[256];
    int tid = threadIdx.x;
    float a1 = 0.0f, a2 = 0.0f;
    for (int i = tid; i < 8192;  i += 256) a1 += __int_as_float(g_rowmin[i]);
    for (int i = tid; i < 16384; i += 256) a2 += __int_as_float(g_rowmin[8192 + i]);

    sh[tid] = a1; __syncthreads();
    for (int s = 128; s > 0; s >>= 1) { if (tid < s) sh[tid] += sh[tid + s]; __syncthreads(); }
    float rs1 = sh[0];
    __syncthreads();
    sh[tid] = a2; __syncthreads();
    for (int s = 128; s > 0; s >>= 1) { if (tid < s) sh[tid] += sh[tid + s]; __syncthreads(); }
    float rs2 = sh[0];

    if (tid == 0) {
        // t-space = dist/2; cd = mean_rowmin_t + mean_colmin_t
        float cd1 = rs1 / 8192.0f  + g_acc[0] / 131072.0f;   // 8*1024, 8*16384
        float cd2 = rs2 / 16384.0f + g_acc[1] / 262144.0f;   // 16*1024, 16*16384
        float consist = g_acc[2] * (1000.0f / 49152.0f);     // mean over T*B*S*D
        out[0] = (cd1 + cd2) / 3.0f + consist;               // /(T+1)
    }
}

extern "C" void kernel_launch(void* const* d_in, const int* in_sizes, int n_in,
                              void* d_out, int out_size) {
    const float* gt  = (const float*)d_in[0];   // [8,16384,3]
    const float* sp  = (const float*)d_in[1];   // [8,1024,3]
    const float* tgt = (const float*)d_in[2];   // [2,8,16384,3] -> 16 batches
    const float* tsp = (const float*)d_in[3];   // [2,8,1024,3]  -> 16 batches
    const float* M   = (const float*)d_in[4];   // [2,3,3]
    (void)in_sizes; (void)n_in; (void)out_size;

    k_pre<<<1, 1024>>>(sp, tsp, M);
    k_chamfer<<<dim3(NP / COLS_PER_BLOCK, 16), WARPS * 32>>>(tsp, tgt, 8192, 1); // big first
    k_chamfer<<<dim3(NP / COLS_PER_BLOCK, 8),  WARPS * 32>>>(sp,  gt,  0,    0);
    k_final<<<1, 256>>>((float*)d_out);
}

// round 4
// speedup vs baseline: 1.9499x; 1.0435x over previous
#include <cuda_runtime.h>

#define SD 1024          // structure points per batch (rows)
#define NP 16384         // gt points per batch (cols)
#define WC 64            // columns per warp
#define WARPS 4
#define COLS_PER_BLOCK (WARPS * WC)   // 256

// scratch (no allocations allowed)
__device__ __align__(16) int g_rowmin[24576]; // 8*1024 (cham1) + 16*1024 (cham2), float bits
__device__ float g_acc[4];                    // [0]=colsum1, [1]=colsum2

__device__ __forceinline__ unsigned long long pack2(float lo, float hi) {
    unsigned long long r;
    asm("mov.b64 %0, {%1, %2};" : "=l"(r) : "f"(lo), "f"(hi));
    return r;
}

// two pairs: q = (nax,nay,naz).(p) + ha + hb (packed f32x2);
// update the two row-mins and the traveling column accumulator.
__device__ __forceinline__ void pair_step(
    unsigned long long nax2, unsigned long long nay2, unsigned long long naz2,
    unsigned long long ha2,
    unsigned long long px2, unsigned long long py2, unsigned long long pz2,
    unsigned long long hb2,
    float& rlo, float& rhi, float& acc)
{
    asm("{\n\t"
        ".reg .b64 q;\n\t"
        ".reg .f32 lo, hi;\n\t"
        "fma.rn.f32x2 q, %5, %9, %6;\n\t"   // naz2*pz2 + ha2
        "fma.rn.f32x2 q, %4, %8, q;\n\t"    // + nay2*py2
        "fma.rn.f32x2 q, %3, %7, q;\n\t"    // + nax2*px2
        "add.rn.f32x2 q, q, %10;\n\t"       // + hb2
        "mov.b64 {lo, hi}, q;\n\t"
        "min.f32 %0, %0, lo;\n\t"
        "min.f32 %1, %1, hi;\n\t"
        "min.f32 %2, %2, lo;\n\t"
        "min.f32 %2, %2, hi;\n\t"
        "}"
        : "+f"(rlo), "+f"(rhi), "+f"(acc)
        : "l"(nax2), "l"(nay2), "l"(naz2), "l"(ha2),
          "l"(px2), "l"(py2), "l"(pz2), "l"(hb2));
}

__global__ __launch_bounds__(1024)
void k_init() {
    int i = blockIdx.x * 1024 + threadIdx.x;
    g_rowmin[i] = 0x7f800000;
    if (i < 4) g_acc[i] = 0.0f;
}

// merged chamfer: blockIdx.y in [0,24): y<16 -> (tsp,tgt) job, y>=16 -> (sp,gt) job
__global__ __launch_bounds__(WARPS * 32)
void k_chamfer(const float* __restrict__ sp,  const float* __restrict__ gt,
               const float* __restrict__ tsp, const float* __restrict__ tgt)
{
    __shared__ ulonglong2 tile2[WARPS][32][2];   // duplicated packs {xx,yy},{zz,hh}

    const int y    = blockIdx.y;
    const int tid  = threadIdx.x;
    const int lane = tid & 31;
    const int warp = tid >> 5;
    const float INF = __int_as_float(0x7f800000);

    const float* pa; const float* pb; int rowoff, acc_idx;
    if (y < 16) { pa = tsp + (size_t)y * SD * 3;       pb = tgt + (size_t)y * NP * 3;
                  rowoff = 8192 + y * SD;              acc_idx = 1; }
    else        { int b = y - 16;
                  pa = sp + (size_t)b * SD * 3;        pb = gt + (size_t)b * NP * 3;
                  rowoff = b * SD;                     acc_idx = 0; }

    // ---- all 1024 rows of this batch in this warp's registers ----
    // lane l holds rows { i*32 + l }, packed in pairs (2i, 2i+1)
    unsigned long long nax2[16], nay2[16], naz2[16], ha2[16];
    float rl[16], rh[16];
#pragma unroll
    for (int i = 0; i < 16; i++) {
        int r0 = (2 * i) * 32 + lane;
        int r1 = r0 + 32;
        float x0 = pa[r0*3+0], y0 = pa[r0*3+1], z0 = pa[r0*3+2];
        float x1 = pa[r1*3+0], y1 = pa[r1*3+1], z1 = pa[r1*3+2];
        nax2[i] = pack2(-x0, -x1);
        nay2[i] = pack2(-y0, -y1);
        naz2[i] = pack2(-z0, -z1);
        ha2[i]  = pack2(0.5f * (x0*x0 + y0*y0 + z0*z0),
                        0.5f * (x1*x1 + y1*y1 + z1*z1));
        rl[i] = INF; rh[i] = INF;
    }

    const int cbase = blockIdx.x * COLS_PER_BLOCK + warp * WC;

    // prefetch first tile's column
    int c = cbase + lane;
    float cx = pb[c*3+0], cy = pb[c*3+1], cz = pb[c*3+2];

    float csum = 0.0f;

#pragma unroll
    for (int t = 0; t < WC / 32; t++) {
        {   // stage duplicated packs: 32 B per column
            float hb = 0.5f * (cx*cx + cy*cy + cz*cz);
            ulonglong2 v0, v1;
            v0.x = pack2(cx, cx); v0.y = pack2(cy, cy);
            v1.x = pack2(cz, cz); v1.y = pack2(hb, hb);
            tile2[warp][lane][0] = v0;
            tile2[warp][lane][1] = v1;
        }
        __syncwarp();
        if (t + 1 < WC / 32) {               // prefetch next tile
            int cn = cbase + (t + 1) * 32 + lane;
            cx = pb[cn*3+0]; cy = pb[cn*3+1]; cz = pb[cn*3+2];
        }

        // systolic: at step j, lane l owns the accumulator for column (j+l)&31,
        // mins its 32 rows into it, then passes it to the next lane.
        float acc = INF;
#pragma unroll 2
        for (int j = 0; j < 32; j++) {
            int idx = (j + lane) & 31;
            ulonglong2 A  = tile2[warp][idx][0];
            ulonglong2 Bv = tile2[warp][idx][1];
#pragma unroll
            for (int i = 0; i < 16; i++)
                pair_step(nax2[i], nay2[i], naz2[i], ha2[i],
                          A.x, A.y, Bv.x, Bv.y, rl[i], rh[i], acc);
            acc = __shfl_sync(0xffffffffu, acc, (lane + 1) & 31);
        }
        // lane l now holds the complete (1024-row) min of column l of this tile
        csum += acc;
        __syncwarp();
    }

    // per-warp sum of column mins -> one atomicAdd
#pragma unroll
    for (int o = 16; o > 0; o >>= 1)
        csum += __shfl_xor_sync(0xffffffffu, csum, o);
    if (lane == 0) atomicAdd(&g_acc[acc_idx], csum);

    // partial row-mins -> global (non-negative floats: int order preserved)
    int* rm = g_rowmin + rowoff;
#pragma unroll
    for (int i = 0; i < 16; i++) {
        int r0 = (2 * i) * 32 + lane;
        atomicMin(&rm[r0],      __float_as_int(rl[i]));
        atomicMin(&rm[r0 + 32], __float_as_int(rh[i]));
    }
}

// finalize: row-min sums (int4 loads) + consistency MSE + combine
__global__ __launch_bounds__(1024)
void k_final(const float* __restrict__ sp,
             const float* __restrict__ tsp,
             const float* __restrict__ M,
             float* __restrict__ out)
{
    int tid = threadIdx.x;

    // consistency: tmp[t,b,s,e] = sum_d sp[b,s,d]*M[t,d,e]; SSE vs tsp
    float e = 0.0f;
#pragma unroll
    for (int k = 0; k < 16; k++) {
        int idx = tid + k * 1024;          // [0, 16384) = T*B*S
        int t  = idx >> 13;
        int bs = idx & 8191;
        const float* p = sp + (size_t)bs * 3;
        float x = p[0], y = p[1], z = p[2];
        const float* m = M + t * 9;
        const float* q = tsp + (size_t)idx * 3;
#pragma unroll
        for (int cc = 0; cc < 3; cc++) {
            float v = fmaf(x, m[cc], fmaf(y, m[3 + cc], z * m[6 + cc]));
            float d = v - q[cc];
            e = fmaf(d, d, e);
        }
    }

    // row-min sums, vectorized: 24576 ints = 6144 int4 (first 2048 = chamfer1)
    const int4* rm4 = (const int4*)g_rowmin;
    float a1 = 0.0f, a2 = 0.0f;
#pragma unroll
    for (int k = 0; k < 6; k++) {
        int i = tid + k * 1024;
        int4 v = rm4[i];
        float s = __int_as_float(v.x) + __int_as_float(v.y)
                + __int_as_float(v.z) + __int_as_float(v.w);
        if (i < 2048) a1 += s; else a2 += s;
    }

    __shared__ float sh[1024];
    sh[tid] = a1; __syncthreads();
    for (int s = 512; s > 0; s >>= 1) { if (tid < s) sh[tid] += sh[tid + s]; __syncthreads(); }
    float rs1 = sh[0]; __syncthreads();
    sh[tid] = a2; __syncthreads();
    for (int s = 512; s > 0; s >>= 1) { if (tid < s) sh[tid] += sh[tid + s]; __syncthreads(); }
    float rs2 = sh[0]; __syncthreads();
    sh[tid] = e; __syncthreads();
    for (int s = 512; s > 0; s >>= 1) { if (tid < s) sh[tid] += sh[tid + s]; __syncthreads(); }

    if (tid == 0) {
        // t-space = dist/2; cd = mean_rowmin_t + mean_colmin_t
        float cd1 = rs1 / 8192.0f  + g_acc[0] / 131072.0f;   // 8*1024, 8*16384
        float cd2 = rs2 / 16384.0f + g_acc[1] / 262144.0f;   // 16*1024, 16*16384
        float consist = sh[0] * (1000.0f / 49152.0f);        // mean over T*B*S*D
        out[0] = (cd1 + cd2) / 3.0f + consist;               // /(T+1)
    }
}

extern "C" void kernel_launch(void* const* d_in, const int* in_sizes, int n_in,
                              void* d_out, int out_size) {
    const float* gt  = (const float*)d_in[0];   // [8,16384,3]
    const float* sp  = (const float*)d_in[1];   // [8,1024,3]
    const float* tgt = (const float*)d_in[2];   // [2,8,16384,3] -> 16 batches
    const float* tsp = (const float*)d_in[3];   // [2,8,1024,3]  -> 16 batches
    const float* M   = (const float*)d_in[4];   // [2,3,3]
    (void)in_sizes; (void)n_in; (void)out_size;

    k_init<<<24, 1024>>>();
    k_chamfer<<<dim3(NP / COLS_PER_BLOCK, 24), WARPS * 32>>>(sp, gt, tsp, tgt);
    k_final<<<1, 1024>>>(sp, tsp, M, (float*)d_out);
}